// round 15
// baseline (speedup 1.0000x reference)
#include <cuda_runtime.h>
#include <cuda.h>
#include <cuda_fp16.h>
#include <math.h>
#include <stdint.h>
#include <dlfcn.h>

// ---------------------------------------------------------------------------
#define BB 2
#define SS 2048
#define HH 1024
#define NHEAD 16
#define HDIM 64
#define ROTD 32
#define CONDD 1024
#define FFD 4096
#define MROWS (BB*SS)
#define EPSF 1e-5f
#define L2E 1.4426950408889634f

// ---------------------------------------------------------------------------
// Scratch (device globals)
// ---------------------------------------------------------------------------
__device__ float g_h [MROWS*HH/2];     // fp16 h
__device__ float g_q [MROWS*HH/2];     // fp16 q (rotated + 1/8-scaled)
__device__ float g_k [MROWS*HH/2];     // fp16 k (rotated)
__device__ float g_v [MROWS*HH/2];     // fp16 v
__device__ float g_ao[MROWS*HH/2];     // fp16 attention out
__device__ float g_x1[MROWS*HH];       // fp32 residual-1
__device__ float g_ff[MROWS*FFD/2];    // fp16 ff hidden
__device__ float g_ada1[BB*2*HH];
__device__ float g_ada2[BB*2*HH];
__device__ float g_rope[SS*ROTD*2];    // (cos,sin) table
__device__ float g_wc[14*1024*1024];   // fp16 transposed weights

// ---------------------------------------------------------------------------
// helpers
// ---------------------------------------------------------------------------
__device__ __forceinline__ void mma16(float* c, const uint32_t* a, const uint32_t* b){
    asm volatile("mma.sync.aligned.m16n8k16.row.col.f32.f16.f16.f32 "
        "{%0,%1,%2,%3}, {%4,%5,%6,%7}, {%8,%9}, {%0,%1,%2,%3};"
        : "+f"(c[0]), "+f"(c[1]), "+f"(c[2]), "+f"(c[3])
        : "r"(a[0]), "r"(a[1]), "r"(a[2]), "r"(a[3]), "r"(b[0]), "r"(b[1]));
}
__device__ __forceinline__ uint32_t sm_u32(const void* p){
    uint32_t a;
    asm("{ .reg .u64 t; cvta.to.shared.u64 t, %1; cvt.u32.u64 %0, t; }" : "=r"(a) : "l"(p));
    return a;
}
__device__ __forceinline__ void ldsm4(uint32_t* r, uint32_t a){
    asm volatile("ldmatrix.sync.aligned.m8n8.x4.shared.b16 {%0,%1,%2,%3}, [%4];"
        : "=r"(r[0]), "=r"(r[1]), "=r"(r[2]), "=r"(r[3]) : "r"(a));
}
__device__ __forceinline__ void ldsm4t(uint32_t* r, uint32_t a){
    asm volatile("ldmatrix.sync.aligned.m8n8.x4.trans.shared.b16 {%0,%1,%2,%3}, [%4];"
        : "=r"(r[0]), "=r"(r[1]), "=r"(r[2]), "=r"(r[3]) : "r"(a));
}
__device__ __forceinline__ uint32_t h2u(float lo, float hi){
    __half2 h = __floats2half2_rn(lo, hi);
    return *(uint32_t*)&h;
}
__device__ __forceinline__ uint32_t ex2h2(uint32_t a){
    uint32_t d;
    asm("ex2.approx.f16x2 %0, %1;" : "=r"(d) : "r"(a));
    return d;
}
// --- TMA / mbarrier (sm_90 generic PTX, legal on compute_103) ---
__device__ __forceinline__ void mbar_init(uint32_t a, uint32_t n){
    asm volatile("mbarrier.init.shared.b64 [%0], %1;" :: "r"(a), "r"(n) : "memory");
}
__device__ __forceinline__ void mbar_wait(uint32_t a, uint32_t ph){
    asm volatile("{\n\t.reg .pred P;\n\tWL%=:\n\t"
                 "mbarrier.try_wait.parity.acquire.cta.shared::cta.b64 P, [%0], %1, 0x989680;\n\t"
                 "@!P bra WL%=;\n\t}" :: "r"(a), "r"(ph) : "memory");
}
__device__ __forceinline__ void expect_tx(uint32_t mbar, uint32_t bytes){
    asm volatile("mbarrier.arrive.expect_tx.shared.b64 _, [%0], %1;"
                 :: "r"(mbar), "r"(bytes) : "memory");
}
__device__ __forceinline__ void tma2d(uint32_t dst, const CUtensorMap* m, int x, int y, uint32_t mbar){
    asm volatile("cp.async.bulk.tensor.2d.shared::cluster.global.tile.mbarrier::complete_tx::bytes"
                 " [%0], [%1, {%2, %3}], [%4];"
                 :: "r"(dst), "l"(m), "r"(x), "r"(y), "r"(mbar) : "memory");
}
__device__ __forceinline__ uint32_t sw(int row, int cbyte){
    return (uint32_t)(row*128) + (uint32_t)(cbyte ^ ((row & 7) << 4));
}

// ---------------------------------------------------------------------------
// prep_kernel: weight cvt+transpose + adaLN conditioning + rope table
// ---------------------------------------------------------------------------
__global__ void prep_kernel(const float* __restrict__ s0, const float* __restrict__ s1,
                            const float* __restrict__ s2, const float* __restrict__ s3,
                            const float* __restrict__ s4, const float* __restrict__ s5,
                            __half* d0, __half* d1, __half* d2, __half* d3,
                            __half* d4, __half* d5,
                            const float* __restrict__ cond,
                            const float* __restrict__ aw1, const float* __restrict__ ab1,
                            const float* __restrict__ aw2, const float* __restrict__ ab2,
                            float* __restrict__ o1, float* __restrict__ o2,
                            float2* __restrict__ ropetab)
{
    int bid = blockIdx.x;
    int tid = threadIdx.x;
    if (bid < 12288){
        __shared__ float tile[32][33];
        const float* src; __half* dst; int K, N, tk, tn;
        if (bid < 4096){
            int widx = bid >> 10, t = bid & 1023;
            K = 1024; N = 1024; tk = t >> 5; tn = t & 31;
            src = (widx==0)?s0:(widx==1)?s1:(widx==2)?s2:s3;
            dst = (widx==0)?d0:(widx==1)?d1:(widx==2)?d2:d3;
        } else if (bid < 8192){
            int t = bid - 4096; K = 1024; N = 4096; tk = t >> 7; tn = t & 127;
            src = s4; dst = d4;
        } else {
            int t = bid - 8192; K = 4096; N = 1024; tk = t >> 5; tn = t & 31;
            src = s5; dst = d5;
        }
        int tx = tid & 31, ty = tid >> 5;
        #pragma unroll
        for (int i = 0; i < 4; i++)
            tile[ty + i*8][tx] = src[(size_t)(tk*32 + ty + i*8) * N + tn*32 + tx];
        __syncthreads();
        #pragma unroll
        for (int i = 0; i < 4; i++)
            dst[(size_t)(tn*32 + ty + i*8) * K + tk*32 + tx] = __float2half_rn(tile[tx][ty + i*8]);
    } else if (bid < 12352){
        int idx = bid - 12288;
        const float* w; const float* bi; float* out;
        if ((idx >> 5) == 0){ w = aw1; bi = ab1; out = o1; }
        else                { w = aw2; bi = ab2; out = o2; }
        int b = (idx >> 4) & 1;
        __shared__ float part[256];
        int col = (idx & 15) * 128 + (tid & 127);
        int kg  = tid >> 7;
        const float* c = cond + b * CONDD;
        float acc = 0.f;
        #pragma unroll 4
        for (int k = kg*512; k < kg*512 + 512; k++)
            acc += c[k] * w[(size_t)k * (2*HH) + col];
        part[tid] = acc;
        __syncthreads();
        if (kg == 0)
            out[b * (2*HH) + col] = bi[col] + part[tid] + part[tid + 128];
    } else {
        int idx = bid - 12352;
        #pragma unroll
        for (int t = 0; t < 4; t++){
            int e = idx*1024 + tid*4 + t;
            int s = e >> 5, j = e & 31;
            float invf = (float)pow(10000.0, -(double)j / (double)ROTD);
            float ang  = (float)s * invf;
            double sd, cd;
            sincos((double)ang, &sd, &cd);
            ropetab[e] = make_float2((float)cd, (float)sd);
        }
    }
}

// ---------------------------------------------------------------------------
// TMA-fed HMMA fp16 GEMM. CTA 256x128, BK=64, 8 warps of 64x64 (4m x 2n),
// 4-stage mbarrier pipeline, SW128 tiles, 1 CTA/SM.
// EPI bits: 1=+residual(fp32), 2=GELU, 8=fp16 out; ropemode 0/1/2
// ---------------------------------------------------------------------------
#define TSTG 49152                    // A 32KB (2x128-row boxes) + B 16KB
#define GSMEM_BYTES (4*TSTG + 2048)

template<int EPI>
__device__ void tgemm_body(const CUtensorMap* ta, const CUtensorMap* tb,
                           const float* __restrict__ bias, const float* __restrict__ res,
                           void* __restrict__ Cv, int N, int K,
                           int row0, int col0,
                           const float2* __restrict__ ropetab, int ropemode)
{
    extern __shared__ __align__(128) char smraw[];
    uint32_t sb    = sm_u32(smraw);
    uint32_t mb    = (sb + 7) & ~7u;              // 4 mbarriers
    uint32_t tile0 = (sb + 64 + 1023) & ~1023u;

    const int tid  = threadIdx.x;
    const int lane = tid & 31;
    const int wid  = tid >> 5;
    const int g    = lane >> 2;
    const int tg   = lane & 3;
    const int wm   = (wid & 3) * 64;      // 0,64,128,192
    const int wn   = (wid >> 2) * 64;     // 0,64
    const int NS   = K / 64;

    const int arow = (lane & 7) + (lane & 8);
    const int acb  = (lane & 16);
    const int brow = (lane & 7) + ((lane & 16) >> 1);
    const int bcb  = (lane & 8) * 2;

    // per-warp constant A sub-tile offset (rows 128..255 -> second box)
    const uint32_t aoff = (wm & 128) ? 16384u : 0u;
    const int wml = wm & 127;             // row within its 128-row box

    if (tid == 0){
        mbar_init(mb, 1); mbar_init(mb + 8, 1); mbar_init(mb + 16, 1); mbar_init(mb + 24, 1);
    }
    __syncthreads();
    if (tid == 0){
        #pragma unroll
        for (int s = 0; s < 4; s++){
            uint32_t bar = mb + s*8;
            expect_tx(bar, TSTG);
            uint32_t tp = tile0 + s*TSTG;
            tma2d(tp,         ta, s*64, row0,       bar);
            tma2d(tp + 16384, ta, s*64, row0 + 128, bar);
            tma2d(tp + 32768, tb, s*64, col0,       bar);
        }
    }

    float acc[4][8][4];
    #pragma unroll
    for (int mi = 0; mi < 4; mi++)
        #pragma unroll
        for (int nj = 0; nj < 8; nj++)
            #pragma unroll
            for (int e = 0; e < 4; e++) acc[mi][nj][e] = 0.f;

    for (int s = 0; s < NS; s++){
        int st = s & 3;
        mbar_wait(mb + st*8, (s >> 2) & 1);
        uint32_t Ab = tile0 + st*TSTG + aoff;
        uint32_t Bb = tile0 + st*TSTG + 32768;
        #pragma unroll
        for (int ks = 0; ks < 4; ks++){
            uint32_t a[4][4], b[4][4];
            #pragma unroll
            for (int mi = 0; mi < 4; mi++)
                ldsm4(a[mi], Ab + sw(wml + mi*16 + arow, ks*32 + acb));
            #pragma unroll
            for (int njp = 0; njp < 4; njp++)
                ldsm4(b[njp], Bb + sw(wn + njp*16 + brow, ks*32 + bcb));
            #pragma unroll
            for (int mi = 0; mi < 4; mi++)
                #pragma unroll
                for (int njp = 0; njp < 4; njp++){
                    mma16(acc[mi][2*njp],   a[mi], &b[njp][0]);
                    mma16(acc[mi][2*njp+1], a[mi], &b[njp][2]);
                }
        }
        __syncthreads();
        if (tid == 0 && s + 4 < NS){
            uint32_t bar = mb + st*8;
            expect_tx(bar, TSTG);
            uint32_t tp = tile0 + st*TSTG;
            tma2d(tp,         ta, (s+4)*64, row0,       bar);
            tma2d(tp + 16384, ta, (s+4)*64, row0 + 128, bar);
            tma2d(tp + 32768, tb, (s+4)*64, col0,       bar);
        }
    }

    #pragma unroll
    for (int mi = 0; mi < 4; mi++){
        int r0 = row0 + wm + mi*16 + g;
        size_t ro0 = (size_t)r0 * N;
        size_t ro1 = (size_t)(r0 + 8) * N;
        #pragma unroll
        for (int nj = 0; nj < 8; nj++){
            int cg = col0 + wn + nj*8 + 2*tg;
            float b0 = bias[cg], b1 = bias[cg+1];
            float v0 = acc[mi][nj][0] + b0;
            float v1 = acc[mi][nj][1] + b1;
            float v2 = acc[mi][nj][2] + b0;
            float v3 = acc[mi][nj][3] + b1;
            if (EPI & 1){
                v0 += res[ro0 + cg]; v1 += res[ro0 + cg + 1];
                v2 += res[ro1 + cg]; v3 += res[ro1 + cg + 1];
            }
            if (EPI & 2){
                v0 = 0.5f*v0*(1.0f + erff(v0*0.7071067811865475f));
                v1 = 0.5f*v1*(1.0f + erff(v1*0.7071067811865475f));
                v2 = 0.5f*v2*(1.0f + erff(v2*0.7071067811865475f));
                v3 = 0.5f*v3*(1.0f + erff(v3*0.7071067811865475f));
            }
            if (ropemode){
                int j = (cg & 63) >> 1;
                float2 cs0 = ropetab[(r0 & (SS-1))*ROTD + j];
                float2 cs1 = ropetab[((r0+8) & (SS-1))*ROTD + j];
                float n0 = v0*cs0.x - v1*cs0.y;
                float n1 = v1*cs0.x + v0*cs0.y;
                float n2 = v2*cs1.x - v3*cs1.y;
                float n3 = v3*cs1.x + v2*cs1.y;
                if (ropemode == 2){
                    n0 *= 0.125f; n1 *= 0.125f; n2 *= 0.125f; n3 *= 0.125f;
                }
                v0 = n0; v1 = n1; v2 = n2; v3 = n3;
            }
            if (EPI & 8){
                __half* C = (__half*)Cv;
                *(__half2*)&C[ro0 + cg] = __floats2half2_rn(v0, v1);
                *(__half2*)&C[ro1 + cg] = __floats2half2_rn(v2, v3);
            } else {
                float* C = (float*)Cv;
                *(float2*)&C[ro0 + cg] = make_float2(v0, v1);
                *(float2*)&C[ro1 + cg] = make_float2(v2, v3);
            }
        }
    }
}

template<int EPI>
__global__ __launch_bounds__(256)
void tgemm_kernel(const __grid_constant__ CUtensorMap ta,
                  const __grid_constant__ CUtensorMap tb,
                  const float* __restrict__ bias, const float* __restrict__ res,
                  void* __restrict__ C, int N, int K)
{
    tgemm_body<EPI>(&ta, &tb, bias, res, C, N, K, blockIdx.y*256, blockIdx.x*128,
                    nullptr, 0);
}

__global__ __launch_bounds__(256)
void tqkv_kernel(const __grid_constant__ CUtensorMap ta,
                 const __grid_constant__ CUtensorMap tw0,
                 const __grid_constant__ CUtensorMap tw1,
                 const __grid_constant__ CUtensorMap tw2,
                 const float* __restrict__ b0, const float* __restrict__ b1, const float* __restrict__ b2,
                 __half* o0, __half* o1, __half* o2,
                 const float2* __restrict__ ropetab)
{
    int row0 = blockIdx.y*256, col0 = blockIdx.x*128;
    if (blockIdx.z == 0)
        tgemm_body<8>(&ta, &tw0, b0, nullptr, o0, HH, HH, row0, col0, ropetab, 2);
    else if (blockIdx.z == 1)
        tgemm_body<8>(&ta, &tw1, b1, nullptr, o1, HH, HH, row0, col0, ropetab, 1);
    else
        tgemm_body<8>(&ta, &tw2, b2, nullptr, o2, HH, HH, row0, col0, nullptr, 0);
}

// ---------------------------------------------------------------------------
// Fused LayerNorm + adaLN modulate -> fp16
// ---------------------------------------------------------------------------
__global__ void ln_mod_kernel(const float* __restrict__ x,
                              const float* __restrict__ gamma,
                              const float* __restrict__ beta,
                              const float* __restrict__ ada,
                              __half* __restrict__ out)
{
    int row = blockIdx.x;
    int bi  = row / SS;
    const float* xr = x + (size_t)row * HH;
    int tid = threadIdx.x;

    float v[4];
    *(float4*)v = *(const float4*)(xr + tid*4);
    float s  = v[0]+v[1]+v[2]+v[3];
    float ss = v[0]*v[0]+v[1]*v[1]+v[2]*v[2]+v[3]*v[3];

    #pragma unroll
    for (int o = 16; o; o >>= 1) {
        s  += __shfl_xor_sync(0xffffffffu, s,  o);
        ss += __shfl_xor_sync(0xffffffffu, ss, o);
    }
    __shared__ float ws[8], wss[8];
    int w = tid >> 5, ln = tid & 31;
    if (ln == 0) { ws[w] = s; wss[w] = ss; }
    __syncthreads();
    s = 0.f; ss = 0.f;
    #pragma unroll
    for (int i = 0; i < 8; i++) { s += ws[i]; ss += wss[i]; }

    float mu  = s * (1.0f/HH);
    float var = ss * (1.0f/HH) - mu*mu;
    float inv = rsqrtf(var + EPSF);

    const float* shiftp = ada + bi * (2*HH);
    const float* scalep = shiftp + HH;

    #pragma unroll
    for (int i = 0; i < 4; i++) {
        int j = tid*4 + i;
        float y = (v[i] - mu) * inv * gamma[j] + beta[j];
        v[i] = y * (1.0f + scalep[j]) + shiftp[j];
    }
    __half2* op = (__half2*)(out + (size_t)row * HH + tid*4);
    op[0] = __floats2half2_rn(v[0], v[1]);
    op[1] = __floats2half2_rn(v[2], v[3]);
}

// ---------------------------------------------------------------------------
// Flash attention (unchanged from round 14), TMA-fed, f16x2-exp softmax.
// ---------------------------------------------------------------------------
#define FQB 16384
#define FKB 8192
#define FSMEM_BYTES (1088 + FQB + 4*FKB)

__global__ __launch_bounds__(256, 2)
void flash_kernel(const __grid_constant__ CUtensorMap tq,
                  const __grid_constant__ CUtensorMap tk,
                  const __grid_constant__ CUtensorMap tv,
                  __half* __restrict__ o)
{
    extern __shared__ __align__(128) char smraw[];
    uint32_t sb    = sm_u32(smraw);
    uint32_t mb    = (sb + 7) & ~7u;
    uint32_t tile0 = (sb + 64 + 1023) & ~1023u;
    uint32_t Qb = tile0;
    uint32_t K0 = tile0 + FQB;
    uint32_t V0 = K0 + 2*FKB;

    const int tid  = threadIdx.x;
    const int lane = tid & 31;
    const int wid  = tid >> 5;
    const int g    = lane >> 2;
    const int tg   = lane & 3;

    const int arow = (lane & 7) + (lane & 8);
    const int acb  = (lane & 16);
    const int brow = (lane & 7) + ((lane & 16) >> 1);
    const int bcb  = (lane & 8) * 2;

    const int q0 = blockIdx.x * 128;
    const int h  = blockIdx.y;
    const int b  = blockIdx.z;
    const int xh = h * HDIM;
    const int yb = b * SS;
    const size_t obase = ((size_t)b * SS) * HH + xh;

    if (tid == 0){
        mbar_init(mb, 1); mbar_init(mb + 8, 1); mbar_init(mb + 16, 1);
    }
    __syncthreads();
    if (tid == 0){
        expect_tx(mb, FQB);
        tma2d(Qb, &tq, xh, yb + q0, mb);
        expect_tx(mb + 8, 2*FKB);
        tma2d(K0,       &tk, xh, yb,      mb + 8);
        tma2d(V0,       &tv, xh, yb,      mb + 8);
        expect_tx(mb + 16, 2*FKB);
        tma2d(K0 + FKB, &tk, xh, yb + 64, mb + 16);
        tma2d(V0 + FKB, &tv, xh, yb + 64, mb + 16);
    }
    mbar_wait(mb, 0);

    float oa[8][4];
    #pragma unroll
    for (int nj = 0; nj < 8; nj++)
        #pragma unroll
        for (int e = 0; e < 4; e++) oa[nj][e] = 0.f;
    float m0 = -1e30f, m1 = -1e30f, l0 = 0.f, l1 = 0.f;

    const int NT = SS / 64;

    for (int s = 0; s < NT; s++){
        int bi2 = s & 1;
        mbar_wait(mb + 8 + bi2*8, (s >> 1) & 1);
        uint32_t Kc = K0 + bi2*FKB;
        uint32_t Vc = V0 + bi2*FKB;

        float c[8][4];
        #pragma unroll
        for (int nj = 0; nj < 8; nj++)
            #pragma unroll
            for (int e = 0; e < 4; e++) c[nj][e] = 0.f;
        #pragma unroll
        for (int ks = 0; ks < 4; ks++){
            uint32_t qa[4];
            ldsm4(qa, Qb + sw(wid*16 + arow, ks*32 + acb));
            #pragma unroll
            for (int njp = 0; njp < 4; njp++){
                uint32_t bk[4];
                ldsm4(bk, Kc + sw(njp*16 + brow, ks*32 + bcb));
                mma16(c[2*njp],   qa, &bk[0]);
                mma16(c[2*njp+1], qa, &bk[2]);
            }
        }

        __half2 rmh = __floats2half2_rn(-60000.f, -60000.f);
        #pragma unroll
        for (int nj = 0; nj < 8; nj++){
            __half2 p = __floats2half2_rn(fmaxf(c[nj][0], c[nj][1]),
                                          fmaxf(c[nj][2], c[nj][3]));
            rmh = __hmax2(rmh, p);
        }
        #pragma unroll
        for (int off = 1; off < 4; off <<= 1){
            uint32_t u = __shfl_xor_sync(0xffffffffu, *(uint32_t*)&rmh, off);
            rmh = __hmax2(rmh, *(__half2*)&u);
        }
        float mn0 = fmaxf(m0, __low2float(rmh));
        float mn1 = fmaxf(m1, __high2float(rmh));
        float al0 = __expf(m0 - mn0), al1 = __expf(m1 - mn1);
        #pragma unroll
        for (int nj = 0; nj < 8; nj++){
            oa[nj][0] *= al0; oa[nj][1] *= al0;
            oa[nj][2] *= al1; oa[nj][3] *= al1;
        }

        float mnl0 = mn0 * L2E, mnl1 = mn1 * L2E;
        __half2 sG = __floats2half2_rn(0.f, 0.f);
        __half2 s8 = __floats2half2_rn(0.f, 0.f);
        #pragma unroll
        for (int ks = 0; ks < 4; ks++){
            uint32_t pa[4];
            pa[0] = ex2h2(h2u(fmaf(c[2*ks][0],   L2E, -mnl0), fmaf(c[2*ks][1],   L2E, -mnl0)));
            pa[1] = ex2h2(h2u(fmaf(c[2*ks][2],   L2E, -mnl1), fmaf(c[2*ks][3],   L2E, -mnl1)));
            pa[2] = ex2h2(h2u(fmaf(c[2*ks+1][0], L2E, -mnl0), fmaf(c[2*ks+1][1], L2E, -mnl0)));
            pa[3] = ex2h2(h2u(fmaf(c[2*ks+1][2], L2E, -mnl1), fmaf(c[2*ks+1][3], L2E, -mnl1)));
            sG = __hadd2(sG, __hadd2(*(__half2*)&pa[0], *(__half2*)&pa[2]));
            s8 = __hadd2(s8, __hadd2(*(__half2*)&pa[1], *(__half2*)&pa[3]));
            #pragma unroll
            for (int njp = 0; njp < 4; njp++){
                uint32_t bv[4];
                ldsm4t(bv, Vc + sw(ks*16 + arow, njp*32 + acb));
                mma16(oa[2*njp],   pa, &bv[0]);
                mma16(oa[2*njp+1], pa, &bv[2]);
            }
        }
        float rs0 = __low2float(sG) + __high2float(sG);
        float rs1 = __low2float(s8) + __high2float(s8);
        #pragma unroll
        for (int off = 1; off < 4; off <<= 1){
            rs0 += __shfl_xor_sync(0xffffffffu, rs0, off);
            rs1 += __shfl_xor_sync(0xffffffffu, rs1, off);
        }
        l0 = l0*al0 + rs0; m0 = mn0;
        l1 = l1*al1 + rs1; m1 = mn1;

        __syncthreads();
        if (tid == 0 && s + 2 < NT){
            uint32_t bar = mb + 8 + bi2*8;
            expect_tx(bar, 2*FKB);
            tma2d(K0 + bi2*FKB, &tk, xh, yb + (s+2)*64, bar);
            tma2d(V0 + bi2*FKB, &tv, xh, yb + (s+2)*64, bar);
        }
    }

    float inv0 = 1.0f / l0, inv1 = 1.0f / l1;
    #pragma unroll
    for (int nj = 0; nj < 8; nj++){
        int col = nj*8 + 2*tg;
        size_t a0 = obase + (size_t)(q0 + wid*16 + g)*HH + col;
        size_t a1 = obase + (size_t)(q0 + wid*16 + g + 8)*HH + col;
        *(__half2*)(o + a0) = __floats2half2_rn(oa[nj][0]*inv0, oa[nj][1]*inv0);
        *(__half2*)(o + a1) = __floats2half2_rn(oa[nj][2]*inv1, oa[nj][3]*inv1);
    }
}

// ---------------------------------------------------------------------------
// Host launcher
// ---------------------------------------------------------------------------
typedef CUresult (*EncodeFn)(CUtensorMap*, CUtensorMapDataType, cuuint32_t, void*,
    const cuuint64_t*, const cuuint64_t*, const cuuint32_t*, const cuuint32_t*,
    CUtensorMapInterleave, CUtensorMapSwizzle, CUtensorMapL2promotion,
    CUtensorMapFloatOOBfill);

static void enc_fp16_2d(EncodeFn f, CUtensorMap* m, void* ptr,
                        uint64_t kdim, uint64_t rows, uint32_t bk, uint32_t brows)
{
    cuuint64_t dims[2]    = {kdim, rows};
    cuuint64_t strides[1] = {kdim * 2};
    cuuint32_t box[2]     = {bk, brows};
    cuuint32_t estr[2]    = {1, 1};
    f(m, CU_TENSOR_MAP_DATA_TYPE_FLOAT16, 2, ptr, dims, strides, box, estr,
      CU_TENSOR_MAP_INTERLEAVE_NONE, CU_TENSOR_MAP_SWIZZLE_128B,
      CU_TENSOR_MAP_L2_PROMOTION_L2_128B, CU_TENSOR_MAP_FLOAT_OOB_FILL_NONE);
}

extern "C" void kernel_launch(void* const* d_in, const int* in_sizes, int n_in,
                              void* d_out, int out_size)
{
    const float* x      = (const float*)d_in[0];
    const float* cond   = (const float*)d_in[1];
    const float* wq     = (const float*)d_in[3];
    const float* bq     = (const float*)d_in[4];
    const float* wk     = (const float*)d_in[5];
    const float* bk     = (const float*)d_in[6];
    const float* wv     = (const float*)d_in[7];
    const float* bv     = (const float*)d_in[8];
    const float* wo     = (const float*)d_in[9];
    const float* bo     = (const float*)d_in[10];
    const float* ln1_g  = (const float*)d_in[11];
    const float* ln1_b  = (const float*)d_in[12];
    const float* ada1_w = (const float*)d_in[13];
    const float* ada1_b = (const float*)d_in[14];
    const float* ln2_g  = (const float*)d_in[15];
    const float* ln2_b  = (const float*)d_in[16];
    const float* ada2_w = (const float*)d_in[17];
    const float* ada2_b = (const float*)d_in[18];
    const float* ff_w1  = (const float*)d_in[19];
    const float* ff_b1  = (const float*)d_in[20];
    const float* ff_w2  = (const float*)d_in[21];
    const float* ff_b2  = (const float*)d_in[22];
    float* out = (float*)d_out;

    float *p_h, *p_q, *p_k, *p_v, *p_ao, *p_x1, *p_ff, *p_a1, *p_a2, *p_wc, *p_rt;
    cudaGetSymbolAddress((void**)&p_h,  g_h);
    cudaGetSymbolAddress((void**)&p_q,  g_q);
    cudaGetSymbolAddress((void**)&p_k,  g_k);
    cudaGetSymbolAddress((void**)&p_v,  g_v);
    cudaGetSymbolAddress((void**)&p_ao, g_ao);
    cudaGetSymbolAddress((void**)&p_x1, g_x1);
    cudaGetSymbolAddress((void**)&p_ff, g_ff);
    cudaGetSymbolAddress((void**)&p_a1, g_ada1);
    cudaGetSymbolAddress((void**)&p_a2, g_ada2);
    cudaGetSymbolAddress((void**)&p_wc, g_wc);
    cudaGetSymbolAddress((void**)&p_rt, g_rope);

    __half* hw = (__half*)p_wc;
    const size_t MW = 1024*1024;
    __half* wq_t = hw;
    __half* wk_t = hw + MW;
    __half* wv_t = hw + 2*MW;
    __half* wo_t = hw + 3*MW;
    __half* w1_t = hw + 4*MW;
    __half* w2_t = hw + 8*MW;

    __half* hh  = (__half*)p_h;
    __half* hq  = (__half*)p_q;
    __half* hk  = (__half*)p_k;
    __half* hv  = (__half*)p_v;
    __half* hao = (__half*)p_ao;
    __half* hff = (__half*)p_ff;

    void* dl = dlopen("libcuda.so.1", RTLD_NOW | RTLD_GLOBAL);
    if (!dl) dl = dlopen("libcuda.so", RTLD_NOW | RTLD_GLOBAL);
    EncodeFn enc = (EncodeFn)dlsym(dl, "cuTensorMapEncodeTiled");

    static CUtensorMap m_h, m_ao, m_ff, m_wq, m_wk, m_wv, m_wo, m_w1, m_w2;
    static CUtensorMap m_fq, m_fk, m_fv;
    enc_fp16_2d(enc, &m_h,  hh,   1024, MROWS, 64, 128);
    enc_fp16_2d(enc, &m_ao, hao,  1024, MROWS, 64, 128);
    enc_fp16_2d(enc, &m_ff, hff,  4096, MROWS, 64, 128);
    enc_fp16_2d(enc, &m_wq, wq_t, 1024, 1024,  64, 128);
    enc_fp16_2d(enc, &m_wk, wk_t, 1024, 1024,  64, 128);
    enc_fp16_2d(enc, &m_wv, wv_t, 1024, 1024,  64, 128);
    enc_fp16_2d(enc, &m_wo, wo_t, 1024, 1024,  64, 128);
    enc_fp16_2d(enc, &m_w1, w1_t, 1024, 4096,  64, 128);
    enc_fp16_2d(enc, &m_w2, w2_t, 4096, 1024,  64, 128);
    enc_fp16_2d(enc, &m_fq, hq,   1024, MROWS, 64, 128);
    enc_fp16_2d(enc, &m_fk, hk,   1024, MROWS, 64, 64);
    enc_fp16_2d(enc, &m_fv, hv,   1024, MROWS, 64, 64);

    cudaFuncSetAttribute(tqkv_kernel,      cudaFuncAttributeMaxDynamicSharedMemorySize, GSMEM_BYTES);
    cudaFuncSetAttribute(tgemm_kernel<1>,  cudaFuncAttributeMaxDynamicSharedMemorySize, GSMEM_BYTES);
    cudaFuncSetAttribute(tgemm_kernel<10>, cudaFuncAttributeMaxDynamicSharedMemorySize, GSMEM_BYTES);
    cudaFuncSetAttribute(flash_kernel,     cudaFuncAttributeMaxDynamicSharedMemorySize, FSMEM_BYTES);

    // 0: prep (weight cvt+T, adaLN conditioning, rope table)
    prep_kernel<<<12416, 256>>>(wq, wk, wv, wo, ff_w1, ff_w2,
                                wq_t, wk_t, wv_t, wo_t, w1_t, w2_t,
                                cond, ada1_w, ada1_b, ada2_w, ada2_b,
                                p_a1, p_a2, (float2*)p_rt);

    // 1: LN1 + modulate -> fp16
    ln_mod_kernel<<<MROWS, 256>>>(x, ln1_g, ln1_b, p_a1, hh);

    // 2: QKV + fused RoPE (q pre-scaled 1/8)
    tqkv_kernel<<<dim3(HH/128, MROWS/256, 3), 256, GSMEM_BYTES>>>(
        m_h, m_wq, m_wk, m_wv, bq, bk, bv, hq, hk, hv, (const float2*)p_rt);

    // 3: attention (TMA-fed)   <-- ncu window
    flash_kernel<<<dim3(SS/128, NHEAD, BB), 256, FSMEM_BYTES>>>(m_fq, m_fk, m_fv, hao);

    // 4: output projection + residual(x) -> fp32 x1
    tgemm_kernel<1><<<dim3(HH/128, MROWS/256), 256, GSMEM_BYTES>>>(
        m_ao, m_wo, bo, x, p_x1, HH, HH);

    // 5: LN2 + modulate -> fp16
    ln_mod_kernel<<<MROWS, 256>>>(p_x1, ln2_g, ln2_b, p_a2, hh);

    // 6: FF1 + GELU -> fp16
    tgemm_kernel<10><<<dim3(FFD/128, MROWS/256), 256, GSMEM_BYTES>>>(
        m_h, m_w1, ff_b1, nullptr, hff, FFD, HH);

    // 7: FF2 + residual(x1) -> fp32 out
    tgemm_kernel<1><<<dim3(HH/128, MROWS/256), 256, GSMEM_BYTES>>>(
        m_ff, m_w2, ff_b2, p_x1, out, HH, FFD);
}

// round 16
// speedup vs baseline: 1.0389x; 1.0389x over previous
#include <cuda_runtime.h>
#include <cuda.h>
#include <cuda_fp16.h>
#include <math.h>
#include <stdint.h>
#include <dlfcn.h>

// ---------------------------------------------------------------------------
#define BB 2
#define SS 2048
#define HH 1024
#define NHEAD 16
#define HDIM 64
#define ROTD 32
#define CONDD 1024
#define FFD 4096
#define MROWS (BB*SS)
#define EPSF 1e-5f
#define L2E 1.4426950408889634f

// ---------------------------------------------------------------------------
// Scratch (device globals)
// ---------------------------------------------------------------------------
__device__ float g_h [MROWS*HH/2];     // fp16 h
__device__ float g_q [MROWS*HH/2];     // fp16 q (rotated + 1/8-scaled)
__device__ float g_k [MROWS*HH/2];     // fp16 k (rotated)
__device__ float g_v [MROWS*HH/2];     // fp16 v
__device__ float g_ao[MROWS*HH/2];     // fp16 attention out
__device__ float g_x1[MROWS*HH];       // fp32 residual-1
__device__ float g_ff[MROWS*FFD/2];    // fp16 ff hidden
__device__ float g_ada1[BB*2*HH];
__device__ float g_ada2[BB*2*HH];
__device__ float g_rope[SS*ROTD*2];    // (cos,sin) table
__device__ float g_wc[14*1024*1024];   // fp16 transposed weights

// ---------------------------------------------------------------------------
// helpers
// ---------------------------------------------------------------------------
__device__ __forceinline__ void mma16(float* c, const uint32_t* a, const uint32_t* b){
    asm volatile("mma.sync.aligned.m16n8k16.row.col.f32.f16.f16.f32 "
        "{%0,%1,%2,%3}, {%4,%5,%6,%7}, {%8,%9}, {%0,%1,%2,%3};"
        : "+f"(c[0]), "+f"(c[1]), "+f"(c[2]), "+f"(c[3])
        : "r"(a[0]), "r"(a[1]), "r"(a[2]), "r"(a[3]), "r"(b[0]), "r"(b[1]));
}
__device__ __forceinline__ uint32_t sm_u32(const void* p){
    uint32_t a;
    asm("{ .reg .u64 t; cvta.to.shared.u64 t, %1; cvt.u32.u64 %0, t; }" : "=r"(a) : "l"(p));
    return a;
}
__device__ __forceinline__ void ldsm4(uint32_t* r, uint32_t a){
    asm volatile("ldmatrix.sync.aligned.m8n8.x4.shared.b16 {%0,%1,%2,%3}, [%4];"
        : "=r"(r[0]), "=r"(r[1]), "=r"(r[2]), "=r"(r[3]) : "r"(a));
}
__device__ __forceinline__ void ldsm4t(uint32_t* r, uint32_t a){
    asm volatile("ldmatrix.sync.aligned.m8n8.x4.trans.shared.b16 {%0,%1,%2,%3}, [%4];"
        : "=r"(r[0]), "=r"(r[1]), "=r"(r[2]), "=r"(r[3]) : "r"(a));
}
__device__ __forceinline__ uint32_t h2u(float lo, float hi){
    __half2 h = __floats2half2_rn(lo, hi);
    return *(uint32_t*)&h;
}
__device__ __forceinline__ uint32_t ex2h2(uint32_t a){
    uint32_t d;
    asm("ex2.approx.f16x2 %0, %1;" : "=r"(d) : "r"(a));
    return d;
}
// --- TMA / mbarrier (sm_90 generic PTX, legal on compute_103) ---
__device__ __forceinline__ void mbar_init(uint32_t a, uint32_t n){
    asm volatile("mbarrier.init.shared.b64 [%0], %1;" :: "r"(a), "r"(n) : "memory");
}
__device__ __forceinline__ void mbar_wait(uint32_t a, uint32_t ph){
    asm volatile("{\n\t.reg .pred P;\n\tWL%=:\n\t"
                 "mbarrier.try_wait.parity.acquire.cta.shared::cta.b64 P, [%0], %1, 0x989680;\n\t"
                 "@!P bra WL%=;\n\t}" :: "r"(a), "r"(ph) : "memory");
}
__device__ __forceinline__ void expect_tx(uint32_t mbar, uint32_t bytes){
    asm volatile("mbarrier.arrive.expect_tx.shared.b64 _, [%0], %1;"
                 :: "r"(mbar), "r"(bytes) : "memory");
}
__device__ __forceinline__ void tma2d(uint32_t dst, const CUtensorMap* m, int x, int y, uint32_t mbar){
    asm volatile("cp.async.bulk.tensor.2d.shared::cluster.global.tile.mbarrier::complete_tx::bytes"
                 " [%0], [%1, {%2, %3}], [%4];"
                 :: "r"(dst), "l"(m), "r"(x), "r"(y), "r"(mbar) : "memory");
}
__device__ __forceinline__ uint32_t sw(int row, int cbyte){
    return (uint32_t)(row*128) + (uint32_t)(cbyte ^ ((row & 7) << 4));
}

// ---------------------------------------------------------------------------
// prep_kernel: weight cvt+transpose + adaLN conditioning + rope table
// ---------------------------------------------------------------------------
__global__ void prep_kernel(const float* __restrict__ s0, const float* __restrict__ s1,
                            const float* __restrict__ s2, const float* __restrict__ s3,
                            const float* __restrict__ s4, const float* __restrict__ s5,
                            __half* d0, __half* d1, __half* d2, __half* d3,
                            __half* d4, __half* d5,
                            const float* __restrict__ cond,
                            const float* __restrict__ aw1, const float* __restrict__ ab1,
                            const float* __restrict__ aw2, const float* __restrict__ ab2,
                            float* __restrict__ o1, float* __restrict__ o2,
                            float2* __restrict__ ropetab)
{
    int bid = blockIdx.x;
    int tid = threadIdx.x;
    if (bid < 12288){
        __shared__ float tile[32][33];
        const float* src; __half* dst; int K, N, tk, tn;
        if (bid < 4096){
            int widx = bid >> 10, t = bid & 1023;
            K = 1024; N = 1024; tk = t >> 5; tn = t & 31;
            src = (widx==0)?s0:(widx==1)?s1:(widx==2)?s2:s3;
            dst = (widx==0)?d0:(widx==1)?d1:(widx==2)?d2:d3;
        } else if (bid < 8192){
            int t = bid - 4096; K = 1024; N = 4096; tk = t >> 7; tn = t & 127;
            src = s4; dst = d4;
        } else {
            int t = bid - 8192; K = 4096; N = 1024; tk = t >> 5; tn = t & 31;
            src = s5; dst = d5;
        }
        int tx = tid & 31, ty = tid >> 5;
        #pragma unroll
        for (int i = 0; i < 4; i++)
            tile[ty + i*8][tx] = src[(size_t)(tk*32 + ty + i*8) * N + tn*32 + tx];
        __syncthreads();
        #pragma unroll
        for (int i = 0; i < 4; i++)
            dst[(size_t)(tn*32 + ty + i*8) * K + tk*32 + tx] = __float2half_rn(tile[tx][ty + i*8]);
    } else if (bid < 12352){
        int idx = bid - 12288;
        const float* w; const float* bi; float* out;
        if ((idx >> 5) == 0){ w = aw1; bi = ab1; out = o1; }
        else                { w = aw2; bi = ab2; out = o2; }
        int b = (idx >> 4) & 1;
        __shared__ float part[256];
        int col = (idx & 15) * 128 + (tid & 127);
        int kg  = tid >> 7;
        const float* c = cond + b * CONDD;
        float acc = 0.f;
        #pragma unroll 4
        for (int k = kg*512; k < kg*512 + 512; k++)
            acc += c[k] * w[(size_t)k * (2*HH) + col];
        part[tid] = acc;
        __syncthreads();
        if (kg == 0)
            out[b * (2*HH) + col] = bi[col] + part[tid] + part[tid + 128];
    } else {
        int idx = bid - 12352;
        #pragma unroll
        for (int t = 0; t < 4; t++){
            int e = idx*1024 + tid*4 + t;
            int s = e >> 5, j = e & 31;
            float invf = (float)pow(10000.0, -(double)j / (double)ROTD);
            float ang  = (float)s * invf;
            double sd, cd;
            sincos((double)ang, &sd, &cd);
            ropetab[e] = make_float2((float)cd, (float)sd);
        }
    }
}

// ---------------------------------------------------------------------------
// TMA-fed HMMA fp16 GEMM. CTA 128x128, 4 warps of 64x64 (2m x 2n), BK=64,
// 3-stage mbarrier pipeline, SW128 tiles, 128 threads, 2 CTAs/SM.
// EPI bits: 1=+residual(fp32), 2=GELU, 8=fp16 out; ropemode 0/1/2
// ---------------------------------------------------------------------------
#define TSTG 32768                    // A 16KB + B 16KB
#define GSMEM_BYTES (3*TSTG + 2048)

template<int EPI>
__device__ void tgemm_body(const CUtensorMap* ta, const CUtensorMap* tb,
                           const float* __restrict__ bias, const float* __restrict__ res,
                           void* __restrict__ Cv, int N, int K,
                           int row0, int col0,
                           const float2* __restrict__ ropetab, int ropemode)
{
    extern __shared__ __align__(128) char smraw[];
    uint32_t sb    = sm_u32(smraw);
    uint32_t mb    = (sb + 7) & ~7u;
    uint32_t tile0 = (sb + 64 + 1023) & ~1023u;

    const int tid  = threadIdx.x;
    const int lane = tid & 31;
    const int wid  = tid >> 5;           // 0..3
    const int g    = lane >> 2;
    const int tg   = lane & 3;
    const int wm   = (wid & 1) * 64;
    const int wn   = (wid >> 1) * 64;
    const int NS   = K / 64;

    const int arow = (lane & 7) + (lane & 8);
    const int acb  = (lane & 16);
    const int brow = (lane & 7) + ((lane & 16) >> 1);
    const int bcb  = (lane & 8) * 2;

    if (tid == 0){
        mbar_init(mb, 1); mbar_init(mb + 8, 1); mbar_init(mb + 16, 1);
    }
    __syncthreads();
    if (tid == 0){
        #pragma unroll
        for (int s = 0; s < 3; s++){
            uint32_t bar = mb + s*8;
            expect_tx(bar, TSTG);
            tma2d(tile0 + s*TSTG,         ta, s*64, row0, bar);
            tma2d(tile0 + s*TSTG + 16384, tb, s*64, col0, bar);
        }
    }

    float acc[4][8][4];
    #pragma unroll
    for (int mi = 0; mi < 4; mi++)
        #pragma unroll
        for (int nj = 0; nj < 8; nj++)
            #pragma unroll
            for (int e = 0; e < 4; e++) acc[mi][nj][e] = 0.f;

    for (int s = 0; s < NS; s++){
        int st = s % 3;
        mbar_wait(mb + st*8, (s/3) & 1);
        uint32_t Ab = tile0 + st*TSTG;
        uint32_t Bb = Ab + 16384;
        #pragma unroll
        for (int ks = 0; ks < 4; ks++){
            uint32_t a[4][4], b[4][4];
            #pragma unroll
            for (int mi = 0; mi < 4; mi++)
                ldsm4(a[mi], Ab + sw(wm + mi*16 + arow, ks*32 + acb));
            #pragma unroll
            for (int njp = 0; njp < 4; njp++)
                ldsm4(b[njp], Bb + sw(wn + njp*16 + brow, ks*32 + bcb));
            #pragma unroll
            for (int mi = 0; mi < 4; mi++)
                #pragma unroll
                for (int njp = 0; njp < 4; njp++){
                    mma16(acc[mi][2*njp],   a[mi], &b[njp][0]);
                    mma16(acc[mi][2*njp+1], a[mi], &b[njp][2]);
                }
        }
        __syncthreads();
        if (tid == 0 && s + 3 < NS){
            uint32_t bar = mb + st*8;
            expect_tx(bar, TSTG);
            tma2d(tile0 + st*TSTG,         ta, (s+3)*64, row0, bar);
            tma2d(tile0 + st*TSTG + 16384, tb, (s+3)*64, col0, bar);
        }
    }

    #pragma unroll
    for (int mi = 0; mi < 4; mi++){
        int r0 = row0 + wm + mi*16 + g;
        size_t ro0 = (size_t)r0 * N;
        size_t ro1 = (size_t)(r0 + 8) * N;
        #pragma unroll
        for (int nj = 0; nj < 8; nj++){
            int cg = col0 + wn + nj*8 + 2*tg;
            float b0 = bias[cg], b1 = bias[cg+1];
            float v0 = acc[mi][nj][0] + b0;
            float v1 = acc[mi][nj][1] + b1;
            float v2 = acc[mi][nj][2] + b0;
            float v3 = acc[mi][nj][3] + b1;
            if (EPI & 1){
                v0 += res[ro0 + cg]; v1 += res[ro0 + cg + 1];
                v2 += res[ro1 + cg]; v3 += res[ro1 + cg + 1];
            }
            if (EPI & 2){
                v0 = 0.5f*v0*(1.0f + erff(v0*0.7071067811865475f));
                v1 = 0.5f*v1*(1.0f + erff(v1*0.7071067811865475f));
                v2 = 0.5f*v2*(1.0f + erff(v2*0.7071067811865475f));
                v3 = 0.5f*v3*(1.0f + erff(v3*0.7071067811865475f));
            }
            if (ropemode){
                int j = (cg & 63) >> 1;
                float2 cs0 = ropetab[(r0 & (SS-1))*ROTD + j];
                float2 cs1 = ropetab[((r0+8) & (SS-1))*ROTD + j];
                float n0 = v0*cs0.x - v1*cs0.y;
                float n1 = v1*cs0.x + v0*cs0.y;
                float n2 = v2*cs1.x - v3*cs1.y;
                float n3 = v3*cs1.x + v2*cs1.y;
                if (ropemode == 2){
                    n0 *= 0.125f; n1 *= 0.125f; n2 *= 0.125f; n3 *= 0.125f;
                }
                v0 = n0; v1 = n1; v2 = n2; v3 = n3;
            }
            if (EPI & 8){
                __half* C = (__half*)Cv;
                *(__half2*)&C[ro0 + cg] = __floats2half2_rn(v0, v1);
                *(__half2*)&C[ro1 + cg] = __floats2half2_rn(v2, v3);
            } else {
                float* C = (float*)Cv;
                *(float2*)&C[ro0 + cg] = make_float2(v0, v1);
                *(float2*)&C[ro1 + cg] = make_float2(v2, v3);
            }
        }
    }
}

template<int EPI>
__global__ __launch_bounds__(128)
void tgemm_kernel(const __grid_constant__ CUtensorMap ta,
                  const __grid_constant__ CUtensorMap tb,
                  const float* __restrict__ bias, const float* __restrict__ res,
                  void* __restrict__ C, int N, int K)
{
    tgemm_body<EPI>(&ta, &tb, bias, res, C, N, K, blockIdx.y*128, blockIdx.x*128,
                    nullptr, 0);
}

__global__ __launch_bounds__(128)
void tqkv_kernel(const __grid_constant__ CUtensorMap ta,
                 const __grid_constant__ CUtensorMap tw0,
                 const __grid_constant__ CUtensorMap tw1,
                 const __grid_constant__ CUtensorMap tw2,
                 const float* __restrict__ b0, const float* __restrict__ b1, const float* __restrict__ b2,
                 __half* o0, __half* o1, __half* o2,
                 const float2* __restrict__ ropetab)
{
    int row0 = blockIdx.y*128, col0 = blockIdx.x*128;
    if (blockIdx.z == 0)
        tgemm_body<8>(&ta, &tw0, b0, nullptr, o0, HH, HH, row0, col0, ropetab, 2);
    else if (blockIdx.z == 1)
        tgemm_body<8>(&ta, &tw1, b1, nullptr, o1, HH, HH, row0, col0, ropetab, 1);
    else
        tgemm_body<8>(&ta, &tw2, b2, nullptr, o2, HH, HH, row0, col0, nullptr, 0);
}

// ---------------------------------------------------------------------------
// Fused LayerNorm + adaLN modulate -> fp16
// ---------------------------------------------------------------------------
__global__ void ln_mod_kernel(const float* __restrict__ x,
                              const float* __restrict__ gamma,
                              const float* __restrict__ beta,
                              const float* __restrict__ ada,
                              __half* __restrict__ out)
{
    int row = blockIdx.x;
    int bi  = row / SS;
    const float* xr = x + (size_t)row * HH;
    int tid = threadIdx.x;

    float v[4];
    *(float4*)v = *(const float4*)(xr + tid*4);
    float s  = v[0]+v[1]+v[2]+v[3];
    float ss = v[0]*v[0]+v[1]*v[1]+v[2]*v[2]+v[3]*v[3];

    #pragma unroll
    for (int o = 16; o; o >>= 1) {
        s  += __shfl_xor_sync(0xffffffffu, s,  o);
        ss += __shfl_xor_sync(0xffffffffu, ss, o);
    }
    __shared__ float ws[8], wss[8];
    int w = tid >> 5, ln = tid & 31;
    if (ln == 0) { ws[w] = s; wss[w] = ss; }
    __syncthreads();
    s = 0.f; ss = 0.f;
    #pragma unroll
    for (int i = 0; i < 8; i++) { s += ws[i]; ss += wss[i]; }

    float mu  = s * (1.0f/HH);
    float var = ss * (1.0f/HH) - mu*mu;
    float inv = rsqrtf(var + EPSF);

    const float* shiftp = ada + bi * (2*HH);
    const float* scalep = shiftp + HH;

    #pragma unroll
    for (int i = 0; i < 4; i++) {
        int j = tid*4 + i;
        float y = (v[i] - mu) * inv * gamma[j] + beta[j];
        v[i] = y * (1.0f + scalep[j]) + shiftp[j];
    }
    __half2* op = (__half2*)(out + (size_t)row * HH + tid*4);
    op[0] = __floats2half2_rn(v[0], v[1]);
    op[1] = __floats2half2_rn(v[2], v[3]);
}

// ---------------------------------------------------------------------------
// Flash attention (unchanged, protected at 113us), TMA-fed, f16x2-exp softmax.
// ---------------------------------------------------------------------------
#define FQB 16384
#define FKB 8192
#define FSMEM_BYTES (1088 + FQB + 4*FKB)

__global__ __launch_bounds__(256, 2)
void flash_kernel(const __grid_constant__ CUtensorMap tq,
                  const __grid_constant__ CUtensorMap tk,
                  const __grid_constant__ CUtensorMap tv,
                  __half* __restrict__ o)
{
    extern __shared__ __align__(128) char smraw[];
    uint32_t sb    = sm_u32(smraw);
    uint32_t mb    = (sb + 7) & ~7u;
    uint32_t tile0 = (sb + 64 + 1023) & ~1023u;
    uint32_t Qb = tile0;
    uint32_t K0 = tile0 + FQB;
    uint32_t V0 = K0 + 2*FKB;

    const int tid  = threadIdx.x;
    const int lane = tid & 31;
    const int wid  = tid >> 5;
    const int g    = lane >> 2;
    const int tg   = lane & 3;

    const int arow = (lane & 7) + (lane & 8);
    const int acb  = (lane & 16);
    const int brow = (lane & 7) + ((lane & 16) >> 1);
    const int bcb  = (lane & 8) * 2;

    const int q0 = blockIdx.x * 128;
    const int h  = blockIdx.y;
    const int b  = blockIdx.z;
    const int xh = h * HDIM;
    const int yb = b * SS;
    const size_t obase = ((size_t)b * SS) * HH + xh;

    if (tid == 0){
        mbar_init(mb, 1); mbar_init(mb + 8, 1); mbar_init(mb + 16, 1);
    }
    __syncthreads();
    if (tid == 0){
        expect_tx(mb, FQB);
        tma2d(Qb, &tq, xh, yb + q0, mb);
        expect_tx(mb + 8, 2*FKB);
        tma2d(K0,       &tk, xh, yb,      mb + 8);
        tma2d(V0,       &tv, xh, yb,      mb + 8);
        expect_tx(mb + 16, 2*FKB);
        tma2d(K0 + FKB, &tk, xh, yb + 64, mb + 16);
        tma2d(V0 + FKB, &tv, xh, yb + 64, mb + 16);
    }
    mbar_wait(mb, 0);

    float oa[8][4];
    #pragma unroll
    for (int nj = 0; nj < 8; nj++)
        #pragma unroll
        for (int e = 0; e < 4; e++) oa[nj][e] = 0.f;
    float m0 = -1e30f, m1 = -1e30f, l0 = 0.f, l1 = 0.f;

    const int NT = SS / 64;

    for (int s = 0; s < NT; s++){
        int bi2 = s & 1;
        mbar_wait(mb + 8 + bi2*8, (s >> 1) & 1);
        uint32_t Kc = K0 + bi2*FKB;
        uint32_t Vc = V0 + bi2*FKB;

        float c[8][4];
        #pragma unroll
        for (int nj = 0; nj < 8; nj++)
            #pragma unroll
            for (int e = 0; e < 4; e++) c[nj][e] = 0.f;
        #pragma unroll
        for (int ks = 0; ks < 4; ks++){
            uint32_t qa[4];
            ldsm4(qa, Qb + sw(wid*16 + arow, ks*32 + acb));
            #pragma unroll
            for (int njp = 0; njp < 4; njp++){
                uint32_t bk[4];
                ldsm4(bk, Kc + sw(njp*16 + brow, ks*32 + bcb));
                mma16(c[2*njp],   qa, &bk[0]);
                mma16(c[2*njp+1], qa, &bk[2]);
            }
        }

        __half2 rmh = __floats2half2_rn(-60000.f, -60000.f);
        #pragma unroll
        for (int nj = 0; nj < 8; nj++){
            __half2 p = __floats2half2_rn(fmaxf(c[nj][0], c[nj][1]),
                                          fmaxf(c[nj][2], c[nj][3]));
            rmh = __hmax2(rmh, p);
        }
        #pragma unroll
        for (int off = 1; off < 4; off <<= 1){
            uint32_t u = __shfl_xor_sync(0xffffffffu, *(uint32_t*)&rmh, off);
            rmh = __hmax2(rmh, *(__half2*)&u);
        }
        float mn0 = fmaxf(m0, __low2float(rmh));
        float mn1 = fmaxf(m1, __high2float(rmh));
        float al0 = __expf(m0 - mn0), al1 = __expf(m1 - mn1);
        #pragma unroll
        for (int nj = 0; nj < 8; nj++){
            oa[nj][0] *= al0; oa[nj][1] *= al0;
            oa[nj][2] *= al1; oa[nj][3] *= al1;
        }

        float mnl0 = mn0 * L2E, mnl1 = mn1 * L2E;
        __half2 sG = __floats2half2_rn(0.f, 0.f);
        __half2 s8 = __floats2half2_rn(0.f, 0.f);
        #pragma unroll
        for (int ks = 0; ks < 4; ks++){
            uint32_t pa[4];
            pa[0] = ex2h2(h2u(fmaf(c[2*ks][0],   L2E, -mnl0), fmaf(c[2*ks][1],   L2E, -mnl0)));
            pa[1] = ex2h2(h2u(fmaf(c[2*ks][2],   L2E, -mnl1), fmaf(c[2*ks][3],   L2E, -mnl1)));
            pa[2] = ex2h2(h2u(fmaf(c[2*ks+1][0], L2E, -mnl0), fmaf(c[2*ks+1][1], L2E, -mnl0)));
            pa[3] = ex2h2(h2u(fmaf(c[2*ks+1][2], L2E, -mnl1), fmaf(c[2*ks+1][3], L2E, -mnl1)));
            sG = __hadd2(sG, __hadd2(*(__half2*)&pa[0], *(__half2*)&pa[2]));
            s8 = __hadd2(s8, __hadd2(*(__half2*)&pa[1], *(__half2*)&pa[3]));
            #pragma unroll
            for (int njp = 0; njp < 4; njp++){
                uint32_t bv[4];
                ldsm4t(bv, Vc + sw(ks*16 + arow, njp*32 + acb));
                mma16(oa[2*njp],   pa, &bv[0]);
                mma16(oa[2*njp+1], pa, &bv[2]);
            }
        }
        float rs0 = __low2float(sG) + __high2float(sG);
        float rs1 = __low2float(s8) + __high2float(s8);
        #pragma unroll
        for (int off = 1; off < 4; off <<= 1){
            rs0 += __shfl_xor_sync(0xffffffffu, rs0, off);
            rs1 += __shfl_xor_sync(0xffffffffu, rs1, off);
        }
        l0 = l0*al0 + rs0; m0 = mn0;
        l1 = l1*al1 + rs1; m1 = mn1;

        __syncthreads();
        if (tid == 0 && s + 2 < NT){
            uint32_t bar = mb + 8 + bi2*8;
            expect_tx(bar, 2*FKB);
            tma2d(K0 + bi2*FKB, &tk, xh, yb + (s+2)*64, bar);
            tma2d(V0 + bi2*FKB, &tv, xh, yb + (s+2)*64, bar);
        }
    }

    float inv0 = 1.0f / l0, inv1 = 1.0f / l1;
    #pragma unroll
    for (int nj = 0; nj < 8; nj++){
        int col = nj*8 + 2*tg;
        size_t a0 = obase + (size_t)(q0 + wid*16 + g)*HH + col;
        size_t a1 = obase + (size_t)(q0 + wid*16 + g + 8)*HH + col;
        *(__half2*)(o + a0) = __floats2half2_rn(oa[nj][0]*inv0, oa[nj][1]*inv0);
        *(__half2*)(o + a1) = __floats2half2_rn(oa[nj][2]*inv1, oa[nj][3]*inv1);
    }
}

// ---------------------------------------------------------------------------
// Host launcher
// ---------------------------------------------------------------------------
typedef CUresult (*EncodeFn)(CUtensorMap*, CUtensorMapDataType, cuuint32_t, void*,
    const cuuint64_t*, const cuuint64_t*, const cuuint32_t*, const cuuint32_t*,
    CUtensorMapInterleave, CUtensorMapSwizzle, CUtensorMapL2promotion,
    CUtensorMapFloatOOBfill);

static void enc_fp16_2d(EncodeFn f, CUtensorMap* m, void* ptr,
                        uint64_t kdim, uint64_t rows, uint32_t bk, uint32_t brows)
{
    cuuint64_t dims[2]    = {kdim, rows};
    cuuint64_t strides[1] = {kdim * 2};
    cuuint32_t box[2]     = {bk, brows};
    cuuint32_t estr[2]    = {1, 1};
    f(m, CU_TENSOR_MAP_DATA_TYPE_FLOAT16, 2, ptr, dims, strides, box, estr,
      CU_TENSOR_MAP_INTERLEAVE_NONE, CU_TENSOR_MAP_SWIZZLE_128B,
      CU_TENSOR_MAP_L2_PROMOTION_L2_128B, CU_TENSOR_MAP_FLOAT_OOB_FILL_NONE);
}

extern "C" void kernel_launch(void* const* d_in, const int* in_sizes, int n_in,
                              void* d_out, int out_size)
{
    const float* x      = (const float*)d_in[0];
    const float* cond   = (const float*)d_in[1];
    const float* wq     = (const float*)d_in[3];
    const float* bq     = (const float*)d_in[4];
    const float* wk     = (const float*)d_in[5];
    const float* bk     = (const float*)d_in[6];
    const float* wv     = (const float*)d_in[7];
    const float* bv     = (const float*)d_in[8];
    const float* wo     = (const float*)d_in[9];
    const float* bo     = (const float*)d_in[10];
    const float* ln1_g  = (const float*)d_in[11];
    const float* ln1_b  = (const float*)d_in[12];
    const float* ada1_w = (const float*)d_in[13];
    const float* ada1_b = (const float*)d_in[14];
    const float* ln2_g  = (const float*)d_in[15];
    const float* ln2_b  = (const float*)d_in[16];
    const float* ada2_w = (const float*)d_in[17];
    const float* ada2_b = (const float*)d_in[18];
    const float* ff_w1  = (const float*)d_in[19];
    const float* ff_b1  = (const float*)d_in[20];
    const float* ff_w2  = (const float*)d_in[21];
    const float* ff_b2  = (const float*)d_in[22];
    float* out = (float*)d_out;

    float *p_h, *p_q, *p_k, *p_v, *p_ao, *p_x1, *p_ff, *p_a1, *p_a2, *p_wc, *p_rt;
    cudaGetSymbolAddress((void**)&p_h,  g_h);
    cudaGetSymbolAddress((void**)&p_q,  g_q);
    cudaGetSymbolAddress((void**)&p_k,  g_k);
    cudaGetSymbolAddress((void**)&p_v,  g_v);
    cudaGetSymbolAddress((void**)&p_ao, g_ao);
    cudaGetSymbolAddress((void**)&p_x1, g_x1);
    cudaGetSymbolAddress((void**)&p_ff, g_ff);
    cudaGetSymbolAddress((void**)&p_a1, g_ada1);
    cudaGetSymbolAddress((void**)&p_a2, g_ada2);
    cudaGetSymbolAddress((void**)&p_wc, g_wc);
    cudaGetSymbolAddress((void**)&p_rt, g_rope);

    __half* hw = (__half*)p_wc;
    const size_t MW = 1024*1024;
    __half* wq_t = hw;
    __half* wk_t = hw + MW;
    __half* wv_t = hw + 2*MW;
    __half* wo_t = hw + 3*MW;
    __half* w1_t = hw + 4*MW;
    __half* w2_t = hw + 8*MW;

    __half* hh  = (__half*)p_h;
    __half* hq  = (__half*)p_q;
    __half* hk  = (__half*)p_k;
    __half* hv  = (__half*)p_v;
    __half* hao = (__half*)p_ao;
    __half* hff = (__half*)p_ff;

    void* dl = dlopen("libcuda.so.1", RTLD_NOW | RTLD_GLOBAL);
    if (!dl) dl = dlopen("libcuda.so", RTLD_NOW | RTLD_GLOBAL);
    EncodeFn enc = (EncodeFn)dlsym(dl, "cuTensorMapEncodeTiled");

    static CUtensorMap m_h, m_ao, m_ff, m_wq, m_wk, m_wv, m_wo, m_w1, m_w2;
    static CUtensorMap m_fq, m_fk, m_fv;
    enc_fp16_2d(enc, &m_h,  hh,   1024, MROWS, 64, 128);
    enc_fp16_2d(enc, &m_ao, hao,  1024, MROWS, 64, 128);
    enc_fp16_2d(enc, &m_ff, hff,  4096, MROWS, 64, 128);
    enc_fp16_2d(enc, &m_wq, wq_t, 1024, 1024,  64, 128);
    enc_fp16_2d(enc, &m_wk, wk_t, 1024, 1024,  64, 128);
    enc_fp16_2d(enc, &m_wv, wv_t, 1024, 1024,  64, 128);
    enc_fp16_2d(enc, &m_wo, wo_t, 1024, 1024,  64, 128);
    enc_fp16_2d(enc, &m_w1, w1_t, 1024, 4096,  64, 128);
    enc_fp16_2d(enc, &m_w2, w2_t, 4096, 1024,  64, 128);
    enc_fp16_2d(enc, &m_fq, hq,   1024, MROWS, 64, 128);
    enc_fp16_2d(enc, &m_fk, hk,   1024, MROWS, 64, 64);
    enc_fp16_2d(enc, &m_fv, hv,   1024, MROWS, 64, 64);

    cudaFuncSetAttribute(tqkv_kernel,      cudaFuncAttributeMaxDynamicSharedMemorySize, GSMEM_BYTES);
    cudaFuncSetAttribute(tgemm_kernel<1>,  cudaFuncAttributeMaxDynamicSharedMemorySize, GSMEM_BYTES);
    cudaFuncSetAttribute(tgemm_kernel<10>, cudaFuncAttributeMaxDynamicSharedMemorySize, GSMEM_BYTES);
    cudaFuncSetAttribute(flash_kernel,     cudaFuncAttributeMaxDynamicSharedMemorySize, FSMEM_BYTES);

    // 0: prep (weight cvt+T, adaLN conditioning, rope table)
    prep_kernel<<<12416, 256>>>(wq, wk, wv, wo, ff_w1, ff_w2,
                                wq_t, wk_t, wv_t, wo_t, w1_t, w2_t,
                                cond, ada1_w, ada1_b, ada2_w, ada2_b,
                                p_a1, p_a2, (float2*)p_rt);

    // 1: LN1 + modulate -> fp16
    ln_mod_kernel<<<MROWS, 256>>>(x, ln1_g, ln1_b, p_a1, hh);

    // 2: QKV + fused RoPE (q pre-scaled 1/8)
    tqkv_kernel<<<dim3(HH/128, MROWS/128, 3), 128, GSMEM_BYTES>>>(
        m_h, m_wq, m_wk, m_wv, bq, bk, bv, hq, hk, hv, (const float2*)p_rt);

    // 3: attention (TMA-fed)   <-- ncu window
    flash_kernel<<<dim3(SS/128, NHEAD, BB), 256, FSMEM_BYTES>>>(m_fq, m_fk, m_fv, hao);

    // 4: output projection + residual(x) -> fp32 x1
    tgemm_kernel<1><<<dim3(HH/128, MROWS/128), 128, GSMEM_BYTES>>>(
        m_ao, m_wo, bo, x, p_x1, HH, HH);

    // 5: LN2 + modulate -> fp16
    ln_mod_kernel<<<MROWS, 256>>>(p_x1, ln2_g, ln2_b, p_a2, hh);

    // 6: FF1 + GELU -> fp16
    tgemm_kernel<10><<<dim3(FFD/128, MROWS/128), 128, GSMEM_BYTES>>>(
        m_h, m_w1, ff_b1, nullptr, hff, FFD, HH);

    // 7: FF2 + residual(x1) -> fp32 out
    tgemm_kernel<1><<<dim3(HH/128, MROWS/128), 128, GSMEM_BYTES>>>(
        m_ff, m_w2, ff_b2, p_x1, out, HH, FFD);
}

// round 17
// speedup vs baseline: 1.0444x; 1.0053x over previous
#include <cuda_runtime.h>
#include <cuda.h>
#include <cuda_fp16.h>
#include <math.h>
#include <stdint.h>
#include <dlfcn.h>

// ---------------------------------------------------------------------------
#define BB 2
#define SS 2048
#define HH 1024
#define NHEAD 16
#define HDIM 64
#define ROTD 32
#define CONDD 1024
#define FFD 4096
#define MROWS (BB*SS)
#define EPSF 1e-5f
#define L2E 1.4426950408889634f

// ---------------------------------------------------------------------------
// Scratch (device globals)
// ---------------------------------------------------------------------------
__device__ float g_h [MROWS*HH/2];     // fp16 h
__device__ float g_q [MROWS*HH/2];     // fp16 q (rotated + 1/8-scaled)
__device__ float g_k [MROWS*HH/2];     // fp16 k (rotated)
__device__ float g_v [MROWS*HH/2];     // fp16 v
__device__ float g_ao[MROWS*HH/2];     // fp16 attention out
__device__ float g_x1[MROWS*HH];       // fp32 residual-1
__device__ float g_ff[MROWS*FFD/2];    // fp16 ff hidden
__device__ float g_ada1[BB*2*HH];
__device__ float g_ada2[BB*2*HH];
__device__ float g_rope[SS*ROTD*2];    // (cos,sin) table
__device__ float g_wc[14*1024*1024];   // fp16 weights (natural [K][N] layout)

// ---------------------------------------------------------------------------
// helpers
// ---------------------------------------------------------------------------
__device__ __forceinline__ void mma16(float* c, const uint32_t* a, const uint32_t* b){
    asm volatile("mma.sync.aligned.m16n8k16.row.col.f32.f16.f16.f32 "
        "{%0,%1,%2,%3}, {%4,%5,%6,%7}, {%8,%9}, {%0,%1,%2,%3};"
        : "+f"(c[0]), "+f"(c[1]), "+f"(c[2]), "+f"(c[3])
        : "r"(a[0]), "r"(a[1]), "r"(a[2]), "r"(a[3]), "r"(b[0]), "r"(b[1]));
}
__device__ __forceinline__ uint32_t sm_u32(const void* p){
    uint32_t a;
    asm("{ .reg .u64 t; cvta.to.shared.u64 t, %1; cvt.u32.u64 %0, t; }" : "=r"(a) : "l"(p));
    return a;
}
__device__ __forceinline__ void ldsm4(uint32_t* r, uint32_t a){
    asm volatile("ldmatrix.sync.aligned.m8n8.x4.shared.b16 {%0,%1,%2,%3}, [%4];"
        : "=r"(r[0]), "=r"(r[1]), "=r"(r[2]), "=r"(r[3]) : "r"(a));
}
__device__ __forceinline__ void ldsm4t(uint32_t* r, uint32_t a){
    asm volatile("ldmatrix.sync.aligned.m8n8.x4.trans.shared.b16 {%0,%1,%2,%3}, [%4];"
        : "=r"(r[0]), "=r"(r[1]), "=r"(r[2]), "=r"(r[3]) : "r"(a));
}
__device__ __forceinline__ uint32_t h2u(float lo, float hi){
    __half2 h = __floats2half2_rn(lo, hi);
    return *(uint32_t*)&h;
}
__device__ __forceinline__ uint32_t ex2h2(uint32_t a){
    uint32_t d;
    asm("ex2.approx.f16x2 %0, %1;" : "=r"(d) : "r"(a));
    return d;
}
// --- TMA / mbarrier ---
__device__ __forceinline__ void mbar_init(uint32_t a, uint32_t n){
    asm volatile("mbarrier.init.shared.b64 [%0], %1;" :: "r"(a), "r"(n) : "memory");
}
__device__ __forceinline__ void mbar_wait(uint32_t a, uint32_t ph){
    asm volatile("{\n\t.reg .pred P;\n\tWL%=:\n\t"
                 "mbarrier.try_wait.parity.acquire.cta.shared::cta.b64 P, [%0], %1, 0x989680;\n\t"
                 "@!P bra WL%=;\n\t}" :: "r"(a), "r"(ph) : "memory");
}
__device__ __forceinline__ void expect_tx(uint32_t mbar, uint32_t bytes){
    asm volatile("mbarrier.arrive.expect_tx.shared.b64 _, [%0], %1;"
                 :: "r"(mbar), "r"(bytes) : "memory");
}
__device__ __forceinline__ void tma2d(uint32_t dst, const CUtensorMap* m, int x, int y, uint32_t mbar){
    asm volatile("cp.async.bulk.tensor.2d.shared::cluster.global.tile.mbarrier::complete_tx::bytes"
                 " [%0], [%1, {%2, %3}], [%4];"
                 :: "r"(dst), "l"(m), "r"(x), "r"(y), "r"(mbar) : "memory");
}
__device__ __forceinline__ uint32_t sw(int row, int cbyte){
    return (uint32_t)(row*128) + (uint32_t)(cbyte ^ ((row & 7) << 4));
}

// ---------------------------------------------------------------------------
// prep_kernel: streaming weight fp32->fp16 cvt (no transpose) + adaLN + rope
// ---------------------------------------------------------------------------
__global__ void prep_kernel(const float* __restrict__ s0, const float* __restrict__ s1,
                            const float* __restrict__ s2, const float* __restrict__ s3,
                            const float* __restrict__ s4, const float* __restrict__ s5,
                            __half* d0, __half* d1, __half* d2, __half* d3,
                            __half* d4, __half* d5,
                            const float* __restrict__ cond,
                            const float* __restrict__ aw1, const float* __restrict__ ab1,
                            const float* __restrict__ aw2, const float* __restrict__ ab2,
                            float* __restrict__ o1, float* __restrict__ o2,
                            float2* __restrict__ ropetab)
{
    int bid = blockIdx.x;
    int tid = threadIdx.x;
    if (bid < 12288){
        const float* src; __half* dst; int rel;
        if      (bid < 1024){ src = s0; dst = d0; rel = bid; }
        else if (bid < 2048){ src = s1; dst = d1; rel = bid - 1024; }
        else if (bid < 3072){ src = s2; dst = d2; rel = bid - 2048; }
        else if (bid < 4096){ src = s3; dst = d3; rel = bid - 3072; }
        else if (bid < 8192){ src = s4; dst = d4; rel = bid - 4096; }
        else                { src = s5; dst = d5; rel = bid - 8192; }
        size_t base = (size_t)rel * 1024 + tid * 4;
        float4 v = *(const float4*)(src + base);
        __half2* dp = (__half2*)(dst + base);
        dp[0] = __floats2half2_rn(v.x, v.y);
        dp[1] = __floats2half2_rn(v.z, v.w);
    } else if (bid < 12352){
        int idx = bid - 12288;
        const float* w; const float* bi; float* out;
        if ((idx >> 5) == 0){ w = aw1; bi = ab1; out = o1; }
        else                { w = aw2; bi = ab2; out = o2; }
        int b = (idx >> 4) & 1;
        __shared__ float part[256];
        int col = (idx & 15) * 128 + (tid & 127);
        int kg  = tid >> 7;
        const float* c = cond + b * CONDD;
        float acc = 0.f;
        #pragma unroll 4
        for (int k = kg*512; k < kg*512 + 512; k++)
            acc += c[k] * w[(size_t)k * (2*HH) + col];
        part[tid] = acc;
        __syncthreads();
        if (kg == 0)
            out[b * (2*HH) + col] = bi[col] + part[tid] + part[tid + 128];
    } else {
        int idx = bid - 12352;
        #pragma unroll
        for (int t = 0; t < 4; t++){
            int e = idx*1024 + tid*4 + t;
            int s = e >> 5, j = e & 31;
            float invf = (float)pow(10000.0, -(double)j / (double)ROTD);
            float ang  = (float)s * invf;
            double sd, cd;
            sincos((double)ang, &sd, &cd);
            ropetab[e] = make_float2((float)cd, (float)sd);
        }
    }
}

// ---------------------------------------------------------------------------
// TMA-fed HMMA fp16 GEMM. CTA 128x128, 4 warps of 64x64, BK=64, 3-stage,
// 128 threads, 2 CTAs/SM. B operand: natural W[K][N] via trans-ldmatrix
// (two [64N x 64K] SW128 boxes per stage — same pattern as flash V).
// EPI bits: 1=+residual(fp32), 2=GELU, 8=fp16 out; ropemode 0/1/2
// ---------------------------------------------------------------------------
#define TSTG 32768                    // A 16KB + B 2x8KB
#define GSMEM_BYTES (3*TSTG + 2048)

template<int EPI>
__device__ void tgemm_body(const CUtensorMap* ta, const CUtensorMap* tb,
                           const float* __restrict__ bias, const float* __restrict__ res,
                           void* __restrict__ Cv, int N, int K,
                           int row0, int col0,
                           const float2* __restrict__ ropetab, int ropemode)
{
    extern __shared__ __align__(128) char smraw[];
    uint32_t sb    = sm_u32(smraw);
    uint32_t mb    = (sb + 7) & ~7u;
    uint32_t tile0 = (sb + 64 + 1023) & ~1023u;

    const int tid  = threadIdx.x;
    const int lane = tid & 31;
    const int wid  = tid >> 5;           // 0..3
    const int g    = lane >> 2;
    const int tg   = lane & 3;
    const int wm   = (wid & 1) * 64;
    const int wn   = (wid >> 1) * 64;
    const int NS   = K / 64;

    const int arow = (lane & 7) + (lane & 8);
    const int acb  = (lane & 16);

    if (tid == 0){
        mbar_init(mb, 1); mbar_init(mb + 8, 1); mbar_init(mb + 16, 1);
    }
    __syncthreads();
    if (tid == 0){
        #pragma unroll
        for (int s = 0; s < 3; s++){
            uint32_t bar = mb + s*8;
            expect_tx(bar, TSTG);
            uint32_t tp = tile0 + s*TSTG;
            tma2d(tp,         ta, s*64, row0, bar);
            tma2d(tp + 16384, tb, col0,      s*64, bar);
            tma2d(tp + 24576, tb, col0 + 64, s*64, bar);
        }
    }

    float acc[4][8][4];
    #pragma unroll
    for (int mi = 0; mi < 4; mi++)
        #pragma unroll
        for (int nj = 0; nj < 8; nj++)
            #pragma unroll
            for (int e = 0; e < 4; e++) acc[mi][nj][e] = 0.f;

    const uint32_t boff = 16384u + (uint32_t)(wn >> 6) * 8192u;

    for (int s = 0; s < NS; s++){
        int st = s % 3;
        mbar_wait(mb + st*8, (s/3) & 1);
        uint32_t Ab = tile0 + st*TSTG;
        uint32_t Bb = Ab + boff;
        #pragma unroll
        for (int ks = 0; ks < 4; ks++){
            uint32_t a[4][4], b[4][4];
            #pragma unroll
            for (int mi = 0; mi < 4; mi++)
                ldsm4(a[mi], Ab + sw(wm + mi*16 + arow, ks*32 + acb));
            #pragma unroll
            for (int njp = 0; njp < 4; njp++)
                ldsm4t(b[njp], Bb + sw(ks*16 + arow, njp*32 + acb));
            #pragma unroll
            for (int mi = 0; mi < 4; mi++)
                #pragma unroll
                for (int njp = 0; njp < 4; njp++){
                    mma16(acc[mi][2*njp],   a[mi], &b[njp][0]);
                    mma16(acc[mi][2*njp+1], a[mi], &b[njp][2]);
                }
        }
        __syncthreads();
        if (tid == 0 && s + 3 < NS){
            uint32_t bar = mb + st*8;
            expect_tx(bar, TSTG);
            uint32_t tp = tile0 + st*TSTG;
            tma2d(tp,         ta, (s+3)*64, row0, bar);
            tma2d(tp + 16384, tb, col0,      (s+3)*64, bar);
            tma2d(tp + 24576, tb, col0 + 64, (s+3)*64, bar);
        }
    }

    #pragma unroll
    for (int mi = 0; mi < 4; mi++){
        int r0 = row0 + wm + mi*16 + g;
        size_t ro0 = (size_t)r0 * N;
        size_t ro1 = (size_t)(r0 + 8) * N;
        #pragma unroll
        for (int nj = 0; nj < 8; nj++){
            int cg = col0 + wn + nj*8 + 2*tg;
            float b0 = bias[cg], b1 = bias[cg+1];
            float v0 = acc[mi][nj][0] + b0;
            float v1 = acc[mi][nj][1] + b1;
            float v2 = acc[mi][nj][2] + b0;
            float v3 = acc[mi][nj][3] + b1;
            if (EPI & 1){
                v0 += res[ro0 + cg]; v1 += res[ro0 + cg + 1];
                v2 += res[ro1 + cg]; v3 += res[ro1 + cg + 1];
            }
            if (EPI & 2){
                v0 = 0.5f*v0*(1.0f + erff(v0*0.7071067811865475f));
                v1 = 0.5f*v1*(1.0f + erff(v1*0.7071067811865475f));
                v2 = 0.5f*v2*(1.0f + erff(v2*0.7071067811865475f));
                v3 = 0.5f*v3*(1.0f + erff(v3*0.7071067811865475f));
            }
            if (ropemode){
                int j = (cg & 63) >> 1;
                float2 cs0 = ropetab[(r0 & (SS-1))*ROTD + j];
                float2 cs1 = ropetab[((r0+8) & (SS-1))*ROTD + j];
                float n0 = v0*cs0.x - v1*cs0.y;
                float n1 = v1*cs0.x + v0*cs0.y;
                float n2 = v2*cs1.x - v3*cs1.y;
                float n3 = v3*cs1.x + v2*cs1.y;
                if (ropemode == 2){
                    n0 *= 0.125f; n1 *= 0.125f; n2 *= 0.125f; n3 *= 0.125f;
                }
                v0 = n0; v1 = n1; v2 = n2; v3 = n3;
            }
            if (EPI & 8){
                __half* C = (__half*)Cv;
                *(__half2*)&C[ro0 + cg] = __floats2half2_rn(v0, v1);
                *(__half2*)&C[ro1 + cg] = __floats2half2_rn(v2, v3);
            } else {
                float* C = (float*)Cv;
                *(float2*)&C[ro0 + cg] = make_float2(v0, v1);
                *(float2*)&C[ro1 + cg] = make_float2(v2, v3);
            }
        }
    }
}

template<int EPI>
__global__ __launch_bounds__(128)
void tgemm_kernel(const __grid_constant__ CUtensorMap ta,
                  const __grid_constant__ CUtensorMap tb,
                  const float* __restrict__ bias, const float* __restrict__ res,
                  void* __restrict__ C, int N, int K)
{
    tgemm_body<EPI>(&ta, &tb, bias, res, C, N, K, blockIdx.y*128, blockIdx.x*128,
                    nullptr, 0);
}

__global__ __launch_bounds__(128)
void tqkv_kernel(const __grid_constant__ CUtensorMap ta,
                 const __grid_constant__ CUtensorMap tw0,
                 const __grid_constant__ CUtensorMap tw1,
                 const __grid_constant__ CUtensorMap tw2,
                 const float* __restrict__ b0, const float* __restrict__ b1, const float* __restrict__ b2,
                 __half* o0, __half* o1, __half* o2,
                 const float2* __restrict__ ropetab)
{
    int row0 = blockIdx.y*128, col0 = blockIdx.x*128;
    if (blockIdx.z == 0)
        tgemm_body<8>(&ta, &tw0, b0, nullptr, o0, HH, HH, row0, col0, ropetab, 2);
    else if (blockIdx.z == 1)
        tgemm_body<8>(&ta, &tw1, b1, nullptr, o1, HH, HH, row0, col0, ropetab, 1);
    else
        tgemm_body<8>(&ta, &tw2, b2, nullptr, o2, HH, HH, row0, col0, nullptr, 0);
}

// ---------------------------------------------------------------------------
// Fused LayerNorm + adaLN modulate -> fp16
// ---------------------------------------------------------------------------
__global__ void ln_mod_kernel(const float* __restrict__ x,
                              const float* __restrict__ gamma,
                              const float* __restrict__ beta,
                              const float* __restrict__ ada,
                              __half* __restrict__ out)
{
    int row = blockIdx.x;
    int bi  = row / SS;
    const float* xr = x + (size_t)row * HH;
    int tid = threadIdx.x;

    float v[4];
    *(float4*)v = *(const float4*)(xr + tid*4);
    float s  = v[0]+v[1]+v[2]+v[3];
    float ss = v[0]*v[0]+v[1]*v[1]+v[2]*v[2]+v[3]*v[3];

    #pragma unroll
    for (int o = 16; o; o >>= 1) {
        s  += __shfl_xor_sync(0xffffffffu, s,  o);
        ss += __shfl_xor_sync(0xffffffffu, ss, o);
    }
    __shared__ float ws[8], wss[8];
    int w = tid >> 5, ln = tid & 31;
    if (ln == 0) { ws[w] = s; wss[w] = ss; }
    __syncthreads();
    s = 0.f; ss = 0.f;
    #pragma unroll
    for (int i = 0; i < 8; i++) { s += ws[i]; ss += wss[i]; }

    float mu  = s * (1.0f/HH);
    float var = ss * (1.0f/HH) - mu*mu;
    float inv = rsqrtf(var + EPSF);

    const float* shiftp = ada + bi * (2*HH);
    const float* scalep = shiftp + HH;

    #pragma unroll
    for (int i = 0; i < 4; i++) {
        int j = tid*4 + i;
        float y = (v[i] - mu) * inv * gamma[j] + beta[j];
        v[i] = y * (1.0f + scalep[j]) + shiftp[j];
    }
    __half2* op = (__half2*)(out + (size_t)row * HH + tid*4);
    op[0] = __floats2half2_rn(v[0], v[1]);
    op[1] = __floats2half2_rn(v[2], v[3]);
}

// ---------------------------------------------------------------------------
// Flash attention (unchanged, protected at 113us), TMA-fed, f16x2-exp softmax.
// ---------------------------------------------------------------------------
#define FQB 16384
#define FKB 8192
#define FSMEM_BYTES (1088 + FQB + 4*FKB)

__global__ __launch_bounds__(256, 2)
void flash_kernel(const __grid_constant__ CUtensorMap tq,
                  const __grid_constant__ CUtensorMap tk,
                  const __grid_constant__ CUtensorMap tv,
                  __half* __restrict__ o)
{
    extern __shared__ __align__(128) char smraw[];
    uint32_t sb    = sm_u32(smraw);
    uint32_t mb    = (sb + 7) & ~7u;
    uint32_t tile0 = (sb + 64 + 1023) & ~1023u;
    uint32_t Qb = tile0;
    uint32_t K0 = tile0 + FQB;
    uint32_t V0 = K0 + 2*FKB;

    const int tid  = threadIdx.x;
    const int lane = tid & 31;
    const int wid  = tid >> 5;
    const int g    = lane >> 2;
    const int tg   = lane & 3;

    const int arow = (lane & 7) + (lane & 8);
    const int acb  = (lane & 16);
    const int brow = (lane & 7) + ((lane & 16) >> 1);
    const int bcb  = (lane & 8) * 2;

    const int q0 = blockIdx.x * 128;
    const int h  = blockIdx.y;
    const int b  = blockIdx.z;
    const int xh = h * HDIM;
    const int yb = b * SS;
    const size_t obase = ((size_t)b * SS) * HH + xh;

    if (tid == 0){
        mbar_init(mb, 1); mbar_init(mb + 8, 1); mbar_init(mb + 16, 1);
    }
    __syncthreads();
    if (tid == 0){
        expect_tx(mb, FQB);
        tma2d(Qb, &tq, xh, yb + q0, mb);
        expect_tx(mb + 8, 2*FKB);
        tma2d(K0,       &tk, xh, yb,      mb + 8);
        tma2d(V0,       &tv, xh, yb,      mb + 8);
        expect_tx(mb + 16, 2*FKB);
        tma2d(K0 + FKB, &tk, xh, yb + 64, mb + 16);
        tma2d(V0 + FKB, &tv, xh, yb + 64, mb + 16);
    }
    mbar_wait(mb, 0);

    float oa[8][4];
    #pragma unroll
    for (int nj = 0; nj < 8; nj++)
        #pragma unroll
        for (int e = 0; e < 4; e++) oa[nj][e] = 0.f;
    float m0 = -1e30f, m1 = -1e30f, l0 = 0.f, l1 = 0.f;

    const int NT = SS / 64;

    for (int s = 0; s < NT; s++){
        int bi2 = s & 1;
        mbar_wait(mb + 8 + bi2*8, (s >> 1) & 1);
        uint32_t Kc = K0 + bi2*FKB;
        uint32_t Vc = V0 + bi2*FKB;

        float c[8][4];
        #pragma unroll
        for (int nj = 0; nj < 8; nj++)
            #pragma unroll
            for (int e = 0; e < 4; e++) c[nj][e] = 0.f;
        #pragma unroll
        for (int ks = 0; ks < 4; ks++){
            uint32_t qa[4];
            ldsm4(qa, Qb + sw(wid*16 + arow, ks*32 + acb));
            #pragma unroll
            for (int njp = 0; njp < 4; njp++){
                uint32_t bk[4];
                ldsm4(bk, Kc + sw(njp*16 + brow, ks*32 + bcb));
                mma16(c[2*njp],   qa, &bk[0]);
                mma16(c[2*njp+1], qa, &bk[2]);
            }
        }

        __half2 rmh = __floats2half2_rn(-60000.f, -60000.f);
        #pragma unroll
        for (int nj = 0; nj < 8; nj++){
            __half2 p = __floats2half2_rn(fmaxf(c[nj][0], c[nj][1]),
                                          fmaxf(c[nj][2], c[nj][3]));
            rmh = __hmax2(rmh, p);
        }
        #pragma unroll
        for (int off = 1; off < 4; off <<= 1){
            uint32_t u = __shfl_xor_sync(0xffffffffu, *(uint32_t*)&rmh, off);
            rmh = __hmax2(rmh, *(__half2*)&u);
        }
        float mn0 = fmaxf(m0, __low2float(rmh));
        float mn1 = fmaxf(m1, __high2float(rmh));
        float al0 = __expf(m0 - mn0), al1 = __expf(m1 - mn1);
        #pragma unroll
        for (int nj = 0; nj < 8; nj++){
            oa[nj][0] *= al0; oa[nj][1] *= al0;
            oa[nj][2] *= al1; oa[nj][3] *= al1;
        }

        float mnl0 = mn0 * L2E, mnl1 = mn1 * L2E;
        __half2 sG = __floats2half2_rn(0.f, 0.f);
        __half2 s8 = __floats2half2_rn(0.f, 0.f);
        #pragma unroll
        for (int ks = 0; ks < 4; ks++){
            uint32_t pa[4];
            pa[0] = ex2h2(h2u(fmaf(c[2*ks][0],   L2E, -mnl0), fmaf(c[2*ks][1],   L2E, -mnl0)));
            pa[1] = ex2h2(h2u(fmaf(c[2*ks][2],   L2E, -mnl1), fmaf(c[2*ks][3],   L2E, -mnl1)));
            pa[2] = ex2h2(h2u(fmaf(c[2*ks+1][0], L2E, -mnl0), fmaf(c[2*ks+1][1], L2E, -mnl0)));
            pa[3] = ex2h2(h2u(fmaf(c[2*ks+1][2], L2E, -mnl1), fmaf(c[2*ks+1][3], L2E, -mnl1)));
            sG = __hadd2(sG, __hadd2(*(__half2*)&pa[0], *(__half2*)&pa[2]));
            s8 = __hadd2(s8, __hadd2(*(__half2*)&pa[1], *(__half2*)&pa[3]));
            #pragma unroll
            for (int njp = 0; njp < 4; njp++){
                uint32_t bv[4];
                ldsm4t(bv, Vc + sw(ks*16 + arow, njp*32 + acb));
                mma16(oa[2*njp],   pa, &bv[0]);
                mma16(oa[2*njp+1], pa, &bv[2]);
            }
        }
        float rs0 = __low2float(sG) + __high2float(sG);
        float rs1 = __low2float(s8) + __high2float(s8);
        #pragma unroll
        for (int off = 1; off < 4; off <<= 1){
            rs0 += __shfl_xor_sync(0xffffffffu, rs0, off);
            rs1 += __shfl_xor_sync(0xffffffffu, rs1, off);
        }
        l0 = l0*al0 + rs0; m0 = mn0;
        l1 = l1*al1 + rs1; m1 = mn1;

        __syncthreads();
        if (tid == 0 && s + 2 < NT){
            uint32_t bar = mb + 8 + bi2*8;
            expect_tx(bar, 2*FKB);
            tma2d(K0 + bi2*FKB, &tk, xh, yb + (s+2)*64, bar);
            tma2d(V0 + bi2*FKB, &tv, xh, yb + (s+2)*64, bar);
        }
    }

    float inv0 = 1.0f / l0, inv1 = 1.0f / l1;
    #pragma unroll
    for (int nj = 0; nj < 8; nj++){
        int col = nj*8 + 2*tg;
        size_t a0 = obase + (size_t)(q0 + wid*16 + g)*HH + col;
        size_t a1 = obase + (size_t)(q0 + wid*16 + g + 8)*HH + col;
        *(__half2*)(o + a0) = __floats2half2_rn(oa[nj][0]*inv0, oa[nj][1]*inv0);
        *(__half2*)(o + a1) = __floats2half2_rn(oa[nj][2]*inv1, oa[nj][3]*inv1);
    }
}

// ---------------------------------------------------------------------------
// Host launcher
// ---------------------------------------------------------------------------
typedef CUresult (*EncodeFn)(CUtensorMap*, CUtensorMapDataType, cuuint32_t, void*,
    const cuuint64_t*, const cuuint64_t*, const cuuint32_t*, const cuuint32_t*,
    CUtensorMapInterleave, CUtensorMapSwizzle, CUtensorMapL2promotion,
    CUtensorMapFloatOOBfill);

static void enc_fp16_2d(EncodeFn f, CUtensorMap* m, void* ptr,
                        uint64_t xdim, uint64_t rows, uint32_t bx, uint32_t brows)
{
    cuuint64_t dims[2]    = {xdim, rows};
    cuuint64_t strides[1] = {xdim * 2};
    cuuint32_t box[2]     = {bx, brows};
    cuuint32_t estr[2]    = {1, 1};
    f(m, CU_TENSOR_MAP_DATA_TYPE_FLOAT16, 2, ptr, dims, strides, box, estr,
      CU_TENSOR_MAP_INTERLEAVE_NONE, CU_TENSOR_MAP_SWIZZLE_128B,
      CU_TENSOR_MAP_L2_PROMOTION_L2_128B, CU_TENSOR_MAP_FLOAT_OOB_FILL_NONE);
}

extern "C" void kernel_launch(void* const* d_in, const int* in_sizes, int n_in,
                              void* d_out, int out_size)
{
    const float* x      = (const float*)d_in[0];
    const float* cond   = (const float*)d_in[1];
    const float* wq     = (const float*)d_in[3];
    const float* bq     = (const float*)d_in[4];
    const float* wk     = (const float*)d_in[5];
    const float* bk     = (const float*)d_in[6];
    const float* wv     = (const float*)d_in[7];
    const float* bv     = (const float*)d_in[8];
    const float* wo     = (const float*)d_in[9];
    const float* bo     = (const float*)d_in[10];
    const float* ln1_g  = (const float*)d_in[11];
    const float* ln1_b  = (const float*)d_in[12];
    const float* ada1_w = (const float*)d_in[13];
    const float* ada1_b = (const float*)d_in[14];
    const float* ln2_g  = (const float*)d_in[15];
    const float* ln2_b  = (const float*)d_in[16];
    const float* ada2_w = (const float*)d_in[17];
    const float* ada2_b = (const float*)d_in[18];
    const float* ff_w1  = (const float*)d_in[19];
    const float* ff_b1  = (const float*)d_in[20];
    const float* ff_w2  = (const float*)d_in[21];
    const float* ff_b2  = (const float*)d_in[22];
    float* out = (float*)d_out;

    float *p_h, *p_q, *p_k, *p_v, *p_ao, *p_x1, *p_ff, *p_a1, *p_a2, *p_wc, *p_rt;
    cudaGetSymbolAddress((void**)&p_h,  g_h);
    cudaGetSymbolAddress((void**)&p_q,  g_q);
    cudaGetSymbolAddress((void**)&p_k,  g_k);
    cudaGetSymbolAddress((void**)&p_v,  g_v);
    cudaGetSymbolAddress((void**)&p_ao, g_ao);
    cudaGetSymbolAddress((void**)&p_x1, g_x1);
    cudaGetSymbolAddress((void**)&p_ff, g_ff);
    cudaGetSymbolAddress((void**)&p_a1, g_ada1);
    cudaGetSymbolAddress((void**)&p_a2, g_ada2);
    cudaGetSymbolAddress((void**)&p_wc, g_wc);
    cudaGetSymbolAddress((void**)&p_rt, g_rope);

    __half* hw = (__half*)p_wc;
    const size_t MW = 1024*1024;
    __half* wq_h = hw;
    __half* wk_h = hw + MW;
    __half* wv_h = hw + 2*MW;
    __half* wo_h = hw + 3*MW;
    __half* w1_h = hw + 4*MW;
    __half* w2_h = hw + 8*MW;

    __half* hh  = (__half*)p_h;
    __half* hq  = (__half*)p_q;
    __half* hk  = (__half*)p_k;
    __half* hv  = (__half*)p_v;
    __half* hao = (__half*)p_ao;
    __half* hff = (__half*)p_ff;

    void* dl = dlopen("libcuda.so.1", RTLD_NOW | RTLD_GLOBAL);
    if (!dl) dl = dlopen("libcuda.so", RTLD_NOW | RTLD_GLOBAL);
    EncodeFn enc = (EncodeFn)dlsym(dl, "cuTensorMapEncodeTiled");

    static CUtensorMap m_h, m_ao, m_ff, m_wq, m_wk, m_wv, m_wo, m_w1, m_w2;
    static CUtensorMap m_fq, m_fk, m_fv;
    // activations: [rows][K], box [64 K, 128 rows]
    enc_fp16_2d(enc, &m_h,  hh,   1024, MROWS, 64, 128);
    enc_fp16_2d(enc, &m_ao, hao,  1024, MROWS, 64, 128);
    enc_fp16_2d(enc, &m_ff, hff,  4096, MROWS, 64, 128);
    // weights: natural [K rows][N], box [64 N, 64 K]
    enc_fp16_2d(enc, &m_wq, wq_h, 1024, 1024, 64, 64);
    enc_fp16_2d(enc, &m_wk, wk_h, 1024, 1024, 64, 64);
    enc_fp16_2d(enc, &m_wv, wv_h, 1024, 1024, 64, 64);
    enc_fp16_2d(enc, &m_wo, wo_h, 1024, 1024, 64, 64);
    enc_fp16_2d(enc, &m_w1, w1_h, 4096, 1024, 64, 64);
    enc_fp16_2d(enc, &m_w2, w2_h, 1024, 4096, 64, 64);
    // flash q/k/v
    enc_fp16_2d(enc, &m_fq, hq,   1024, MROWS, 64, 128);
    enc_fp16_2d(enc, &m_fk, hk,   1024, MROWS, 64, 64);
    enc_fp16_2d(enc, &m_fv, hv,   1024, MROWS, 64, 64);

    cudaFuncSetAttribute(tqkv_kernel,      cudaFuncAttributeMaxDynamicSharedMemorySize, GSMEM_BYTES);
    cudaFuncSetAttribute(tgemm_kernel<1>,  cudaFuncAttributeMaxDynamicSharedMemorySize, GSMEM_BYTES);
    cudaFuncSetAttribute(tgemm_kernel<10>, cudaFuncAttributeMaxDynamicSharedMemorySize, GSMEM_BYTES);
    cudaFuncSetAttribute(flash_kernel,     cudaFuncAttributeMaxDynamicSharedMemorySize, FSMEM_BYTES);

    // 0: prep (streaming weight cvt, adaLN conditioning, rope table)
    prep_kernel<<<12416, 256>>>(wq, wk, wv, wo, ff_w1, ff_w2,
                                wq_h, wk_h, wv_h, wo_h, w1_h, w2_h,
                                cond, ada1_w, ada1_b, ada2_w, ada2_b,
                                p_a1, p_a2, (float2*)p_rt);

    // 1: LN1 + modulate -> fp16
    ln_mod_kernel<<<MROWS, 256>>>(x, ln1_g, ln1_b, p_a1, hh);

    // 2: QKV + fused RoPE (q pre-scaled 1/8)
    tqkv_kernel<<<dim3(HH/128, MROWS/128, 3), 128, GSMEM_BYTES>>>(
        m_h, m_wq, m_wk, m_wv, bq, bk, bv, hq, hk, hv, (const float2*)p_rt);

    // 3: attention (TMA-fed)   <-- ncu window
    flash_kernel<<<dim3(SS/128, NHEAD, BB), 256, FSMEM_BYTES>>>(m_fq, m_fk, m_fv, hao);

    // 4: output projection + residual(x) -> fp32 x1
    tgemm_kernel<1><<<dim3(HH/128, MROWS/128), 128, GSMEM_BYTES>>>(
        m_ao, m_wo, bo, x, p_x1, HH, HH);

    // 5: LN2 + modulate -> fp16
    ln_mod_kernel<<<MROWS, 256>>>(p_x1, ln2_g, ln2_b, p_a2, hh);

    // 6: FF1 + GELU -> fp16
    tgemm_kernel<10><<<dim3(FFD/128, MROWS/128), 128, GSMEM_BYTES>>>(
        m_h, m_w1, ff_b1, nullptr, hff, FFD, HH);

    // 7: FF2 + residual(x1) -> fp32 out
    tgemm_kernel<1><<<dim3(HH/128, MROWS/128), 128, GSMEM_BYTES>>>(
        m_ff, m_w2, ff_b2, p_x1, out, HH, FFD);
}